// round 1
// baseline (speedup 1.0000x reference)
#include <cuda_runtime.h>
#include <math.h>

#define NQ 4096
#define NS 4096
#define D  1024
#define KC 128
#define EPSF 1e-12f
#define NGROUP 16   // sample groups for deterministic mus partials
#define NSPLIT 8    // split-K for dots GEMM

// ---------------- device scratch (no allocations allowed) ----------------
__device__ float d_s2[NS];
__device__ float d_q2[NQ];
__device__ float d_selfdot[NQ];
__device__ int   d_cnt[KC];
__device__ float d_S2c[KC];
__device__ float d_musp[NGROUP * KC * D];    // per-group class-sum partials
__device__ float d_mus[KC * D];
__device__ float d_mus2[KC];
__device__ float d_pn2[KC];
__device__ float d_invc[KC];
__device__ float d_dotsp[NSPLIT * NQ * KC];  // split-K partials
__device__ float d_dots[NQ * KC];
__device__ float d_perq[NQ];

// ---------------- reduction helpers (fixed-order, deterministic) ----------
__device__ __forceinline__ float wsum(float v) {
#pragma unroll
    for (int o = 16; o; o >>= 1) v += __shfl_xor_sync(0xffffffffu, v, o);
    return v;
}
__device__ __forceinline__ float wmax(float v) {
#pragma unroll
    for (int o = 16; o; o >>= 1) v = fmaxf(v, __shfl_xor_sync(0xffffffffu, v, o));
    return v;
}

// ---------------- K1: per-row norms + self dot ----------------------------
// grid NQ, block 128.  s2[i]=|xs_i|^2, q2[i]=|xq_i|^2, selfdot[i]=xq_i.xs[pos_i]
__global__ void k_norms(const float* __restrict__ xq, const float* __restrict__ xs,
                        const int* __restrict__ pos) {
    int i = blockIdx.x, t = threadIdx.x;
    int p = pos[i];
    const float4* xr = (const float4*)(xs + (size_t)i * D);
    const float4* qr = (const float4*)(xq + (size_t)i * D);
    const float4* pr = (const float4*)(xs + (size_t)p * D);
    float s2 = 0.f, q2 = 0.f, sd = 0.f;
#pragma unroll
    for (int l = 0; l < 2; l++) {
        int idx = t + l * 128;
        float4 a = xr[idx];
        s2 += a.x * a.x + a.y * a.y + a.z * a.z + a.w * a.w;
        float4 q = qr[idx];
        q2 += q.x * q.x + q.y * q.y + q.z * q.z + q.w * q.w;
        float4 b = pr[idx];
        sd += q.x * b.x + q.y * b.y + q.z * b.z + q.w * b.w;
    }
    __shared__ float sh[3][4];
    int w = t >> 5, ln = t & 31;
    s2 = wsum(s2); q2 = wsum(q2); sd = wsum(sd);
    if (!ln) { sh[0][w] = s2; sh[1][w] = q2; sh[2][w] = sd; }
    __syncthreads();
    if (t == 0) {
        d_s2[i]      = sh[0][0] + sh[0][1] + sh[0][2] + sh[0][3];
        d_q2[i]      = sh[1][0] + sh[1][1] + sh[1][2] + sh[1][3];
        d_selfdot[i] = sh[2][0] + sh[2][1] + sh[2][2] + sh[2][3];
    }
}

// ---------------- K2: per-class count + sum of s2 (deterministic scan) ----
// grid KC, block 256
__global__ void k_class(const int* __restrict__ ys) {
    int c = blockIdx.x, t = threadIdx.x;
    int cnt = 0; float s = 0.f;
    for (int j = t; j < NS; j += 256) {
        if (ys[j] == c) { cnt++; s += d_s2[j]; }
    }
    __shared__ float sf[8];
    __shared__ int   si[8];
    int w = t >> 5, ln = t & 31;
    s = wsum(s);
#pragma unroll
    for (int o = 16; o; o >>= 1) cnt += __shfl_xor_sync(0xffffffffu, cnt, o);
    if (!ln) { sf[w] = s; si[w] = cnt; }
    __syncthreads();
    if (t == 0) {
        float ts = 0.f; int tc = 0;
#pragma unroll
        for (int k = 0; k < 8; k++) { ts += sf[k]; tc += si[k]; }
        d_S2c[c] = ts; d_cnt[c] = tc;
    }
}

// ---------------- K3: per-class feature sums, group partials --------------
// grid (KC, NGROUP), block 256.  Each thread owns 4 contiguous dims.
__global__ void k_musp(const float* __restrict__ xs, const int* __restrict__ ys) {
    int c = blockIdx.x, g = blockIdx.y, t = threadIdx.x;
    __shared__ int sy[NS / NGROUP];  // 256
    sy[t] = ys[g * 256 + t];
    __syncthreads();
    float4 acc = make_float4(0.f, 0.f, 0.f, 0.f);
    for (int jj = 0; jj < 256; jj++) {
        if (sy[jj] == c) {
            float4 v = *(const float4*)(xs + (size_t)(g * 256 + jj) * D + t * 4);
            acc.x += v.x; acc.y += v.y; acc.z += v.z; acc.w += v.w;
        }
    }
    ((float4*)(d_musp + ((size_t)g * KC + c) * D))[t] = acc;
}

// grid KC*D/256, block 256: fixed-order reduction of group partials
__global__ void k_mus_red() {
    int idx = blockIdx.x * 256 + threadIdx.x;
    float s = 0.f;
#pragma unroll
    for (int g = 0; g < NGROUP; g++) s += d_musp[(size_t)g * (KC * D) + idx];
    d_mus[idx] = s;
}

// ---------------- K4: |mus_c|^2, prototype norms, 1/clip(cnt) -------------
// grid KC, block 128
__global__ void k_pn() {
    int c = blockIdx.x, t = threadIdx.x;
    const float4* mr = (const float4*)(d_mus + (size_t)c * D);
    float m2 = 0.f;
#pragma unroll
    for (int l = 0; l < 2; l++) {
        float4 a = mr[t + l * 128];
        m2 += a.x * a.x + a.y * a.y + a.z * a.z + a.w * a.w;
    }
    __shared__ float sh[4];
    int w = t >> 5, ln = t & 31;
    m2 = wsum(m2);
    if (!ln) sh[w] = m2;
    __syncthreads();
    if (t == 0) {
        float tot = sh[0] + sh[1] + sh[2] + sh[3];
        d_mus2[c] = tot;
        float cc = fmaxf((float)d_cnt[c], 0.1f);
        d_invc[c] = 1.f / cc;
        d_pn2[c] = tot / (cc * cc);
    }
}

// ---------------- K5: dots = XQ @ MUS^T (split-K, fp32) -------------------
// grid (NQ/128, NSPLIT), block 256. 128x128 tile, 8x8 per thread.
__global__ __launch_bounds__(256) void k_dots(const float* __restrict__ xq) {
    __shared__ float As[8][128];
    __shared__ float Bs[8][128];
    int qb = blockIdx.x * 128;
    int ks = blockIdx.y;
    int t = threadIdx.x;
    int tx = t & 15, ty = t >> 4;
    float acc[8][8];
#pragma unroll
    for (int a = 0; a < 8; a++)
#pragma unroll
        for (int b = 0; b < 8; b++) acc[a][b] = 0.f;

    for (int kk = 0; kk < D / NSPLIT; kk += 8) {
        int kb = ks * (D / NSPLIT) + kk;
        __syncthreads();
#pragma unroll
        for (int l = 0; l < 4; l++) {
            int lin = t + 256 * l;
            int q = lin >> 3, k = lin & 7;
            As[k][q] = xq[(size_t)(qb + q) * D + kb + k];
            Bs[k][q] = d_mus[(size_t)q * D + kb + k];
        }
        __syncthreads();
#pragma unroll
        for (int k = 0; k < 8; k++) {
            float4 a0 = ((float4*)As[k])[ty];
            float4 a1 = ((float4*)As[k])[16 + ty];
            float4 b0 = ((float4*)Bs[k])[tx];
            float4 b1 = ((float4*)Bs[k])[16 + tx];
            float av[8] = {a0.x, a0.y, a0.z, a0.w, a1.x, a1.y, a1.z, a1.w};
            float bv[8] = {b0.x, b0.y, b0.z, b0.w, b1.x, b1.y, b1.z, b1.w};
#pragma unroll
            for (int ri = 0; ri < 8; ri++)
#pragma unroll
                for (int ci = 0; ci < 8; ci++) acc[ri][ci] += av[ri] * bv[ci];
        }
    }
#pragma unroll
    for (int ri = 0; ri < 8; ri++) {
        int row = qb + ((ri < 4) ? (ty * 4 + ri) : (64 + ty * 4 + ri - 4));
        float4* o = (float4*)(d_dotsp + ((size_t)ks * NQ + row) * KC);
        o[tx]      = make_float4(acc[ri][0], acc[ri][1], acc[ri][2], acc[ri][3]);
        o[16 + tx] = make_float4(acc[ri][4], acc[ri][5], acc[ri][6], acc[ri][7]);
    }
}

// grid NQ*KC/256, block 256: fixed-order split-K reduction
__global__ void k_dots_red() {
    int idx = blockIdx.x * 256 + threadIdx.x;
    float s = 0.f;
#pragma unroll
    for (int p = 0; p < NSPLIT; p++) s += d_dotsp[(size_t)p * (NQ * KC) + idx];
    d_dots[idx] = s;
}

// ---------------- K6: per-query logits + logsumexp + pos_logit ------------
// grid NQ, block KC(=128). Thread k owns class k.
__global__ void k_finalize(const int* __restrict__ yq, const int* __restrict__ ys,
                           const int* __restrict__ pos) {
    int i = blockIdx.x, k = threadIdx.x;
    float q2 = d_q2[i];
    int p = pos[i];
    int cnew = ys[p];
    float dot = d_dots[(size_t)i * KC + k];
    float logit;
    if (k == cnew) {
        // leave-one-out prototype distance (diag override)
        float Cc = fmaxf((float)d_cnt[cnew] - 1.f, 0.1f);
        float qp = (dot - q2) / Cc;                              // xq . proto
        float pp2 = (d_mus2[cnew] - 2.f * dot + q2) / (Cc * Cc); // |proto|^2
        float dp2 = q2 - 2.f * qp + pp2;
        logit = -sqrtf(fmaxf(dp2, 0.f) + EPSF);
    } else {
        float d2 = fmaxf(q2 + d_pn2[k] - 2.f * dot * d_invc[k], 0.f);
        logit = -sqrtf(d2 + EPSF);
    }
    // block logsumexp over 128 lanes
    __shared__ float sh[4];
    int w = k >> 5, ln = k & 31;
    float m = wmax(logit);
    if (!ln) sh[w] = m;
    __syncthreads();
    float mall = fmaxf(fmaxf(sh[0], sh[1]), fmaxf(sh[2], sh[3]));
    float e = expf(logit - mall);
    float s = wsum(e);
    __syncthreads();
    if (!ln) sh[w] = s;
    __syncthreads();
    if (k == 0) {
        float tot = sh[0] + sh[1] + sh[2] + sh[3];
        float neg = mall + logf(tot);

        // pos_logit in closed form
        int cq = yq[i];
        float dotq = d_dots[(size_t)i * KC + cq];
        int cntq = d_cnt[cq];
        float sumd2 = (float)cntq * q2 + d_S2c[cq] - 2.f * dotq;
        bool cmpos = (cq == cnew);         // yq[i] == ys[pos[i]]
        bool idx = cntq > 1;
        float numer = sumd2;
        float denom = (float)cntq;
        if (cmpos) {
            float d2self = fmaxf(q2 + d_s2[p] - 2.f * d_selfdot[i], 0.f);
            numer -= d2self;
            denom -= 1.f;
            if (!idx) denom += 1.f;
        }
        float poslog = (denom > 0.f) ? (-0.5f * numer / denom) : 0.f;
        d_perq[i] = neg - poslog;
    }
}

// ---------------- K7: deterministic final mean ----------------------------
__global__ void k_loss(float* __restrict__ out) {
    int t = threadIdx.x;
    __shared__ float sh[1024];
    float v = d_perq[t] + d_perq[t + 1024] + d_perq[t + 2048] + d_perq[t + 3072];
    sh[t] = v;
    __syncthreads();
    for (int s = 512; s; s >>= 1) {
        if (t < s) sh[t] += sh[t + s];
        __syncthreads();
    }
    if (t == 0) out[0] = sh[0] * (1.f / (float)NQ);
}

// --------------------------------------------------------------------------
extern "C" void kernel_launch(void* const* d_in, const int* in_sizes, int n_in,
                              void* d_out, int out_size) {
    const float* xq  = (const float*)d_in[0];
    const int*   yq  = (const int*)d_in[1];
    const float* xs  = (const float*)d_in[2];
    const int*   ys  = (const int*)d_in[3];
    const int*   pos = (const int*)d_in[4];
    float* out = (float*)d_out;

    k_norms<<<NQ, 128>>>(xq, xs, pos);
    k_class<<<KC, 256>>>(ys);
    k_musp<<<dim3(KC, NGROUP), 256>>>(xs, ys);
    k_mus_red<<<(KC * D) / 256, 256>>>();
    k_pn<<<KC, 128>>>();
    k_dots<<<dim3(NQ / 128, NSPLIT), 256>>>(xq);
    k_dots_red<<<(NQ * KC) / 256, 256>>>();
    k_finalize<<<NQ, KC>>>(yq, ys, pos);
    k_loss<<<1, 1024>>>(out);
}

// round 2
// speedup vs baseline: 1.7536x; 1.7536x over previous
#include <cuda_runtime.h>
#include <math.h>
#include <stdint.h>

#define NQ 4096
#define NS 4096
#define D  1024
#define KC 128
#define EPSF 1e-12f
#define KSP 4            // split-K for dots GEMM
#define KPB (D / KSP)    // 256 K per split
#define CH  32           // K chunk

// ---------------- device scratch ----------------
__device__ float d_s2[NS];
__device__ float d_q2[NQ];
__device__ float d_selfdot[NQ];
__device__ int   d_cnt[KC];
__device__ float d_S2c[KC];
__device__ float d_mus[KC * D];
__device__ float d_mus2[KC];
__device__ float d_pn2[KC];
__device__ float d_invc[KC];
__device__ float d_dotsp[KSP * NQ * KC];   // split-K partials
__device__ float d_perq[NQ];

// ---------------- helpers ----------------
__device__ __forceinline__ float wsum(float v) {
#pragma unroll
    for (int o = 16; o; o >>= 1) v += __shfl_xor_sync(0xffffffffu, v, o);
    return v;
}
__device__ __forceinline__ float wmax(float v) {
#pragma unroll
    for (int o = 16; o; o >>= 1) v = fmaxf(v, __shfl_xor_sync(0xffffffffu, v, o));
    return v;
}
__device__ __forceinline__ uint32_t f2tf32(float f) {
    uint32_t r;
    asm("cvt.rna.tf32.f32 %0, %1;" : "=r"(r) : "f"(f));
    return r;
}

// ---------------- K1: per-row norms + self dot ----------------------------
__global__ void k_norms(const float* __restrict__ xq, const float* __restrict__ xs,
                        const int* __restrict__ pos) {
    int i = blockIdx.x, t = threadIdx.x;
    int p = pos[i];
    const float4* xr = (const float4*)(xs + (size_t)i * D);
    const float4* qr = (const float4*)(xq + (size_t)i * D);
    const float4* pr = (const float4*)(xs + (size_t)p * D);
    float s2 = 0.f, q2 = 0.f, sd = 0.f;
#pragma unroll
    for (int l = 0; l < 2; l++) {
        int idx = t + l * 128;
        float4 a = xr[idx];
        s2 += a.x * a.x + a.y * a.y + a.z * a.z + a.w * a.w;
        float4 q = qr[idx];
        q2 += q.x * q.x + q.y * q.y + q.z * q.z + q.w * q.w;
        float4 b = pr[idx];
        sd += q.x * b.x + q.y * b.y + q.z * b.z + q.w * b.w;
    }
    __shared__ float sh[3][4];
    int w = t >> 5, ln = t & 31;
    s2 = wsum(s2); q2 = wsum(q2); sd = wsum(sd);
    if (!ln) { sh[0][w] = s2; sh[1][w] = q2; sh[2][w] = sd; }
    __syncthreads();
    if (t == 0) {
        d_s2[i]      = sh[0][0] + sh[0][1] + sh[0][2] + sh[0][3];
        d_q2[i]      = sh[1][0] + sh[1][1] + sh[1][2] + sh[1][3];
        d_selfdot[i] = sh[2][0] + sh[2][1] + sh[2][2] + sh[2][3];
    }
}

// ---------------- K2: fused per-class stats + feature sums ----------------
// grid KC, block 256. Ordered compaction of class rows, then direct
// accumulation of mus, cnt, S2c, |mus|^2, pn2, invc. Fully deterministic.
__global__ __launch_bounds__(256) void k_mus(const float* __restrict__ xs,
                                             const int* __restrict__ ys) {
    int c = blockIdx.x, t = threadIdx.x;
    __shared__ int rows[NS];       // ordered row list (worst case all rows)
    __shared__ int sc[256];
    __shared__ float red[256];

    // each thread scans 16 contiguous labels
    int myy[16];
    int j0 = t * 16;
#pragma unroll
    for (int j = 0; j < 16; j++) myy[j] = ys[j0 + j];
    int count = 0;
#pragma unroll
    for (int j = 0; j < 16; j++) count += (myy[j] == c);

    sc[t] = count;
    __syncthreads();
    // Hillis-Steele inclusive scan (deterministic)
    for (int o = 1; o < 256; o <<= 1) {
        int v = (t >= o) ? sc[t - o] : 0;
        __syncthreads();
        sc[t] += v;
        __syncthreads();
    }
    int off = sc[t] - count;
    int cnt = sc[255];
    // ordered write of matching rows
#pragma unroll
    for (int j = 0; j < 16; j++) {
        if (myy[j] == c) rows[off++] = j0 + j;
    }
    __syncthreads();

    // accumulate class feature sum; thread owns dims [4t, 4t+3]
    float4 acc = make_float4(0.f, 0.f, 0.f, 0.f);
    for (int r = 0; r < cnt; r++) {
        float4 v = ((const float4*)(xs + (size_t)rows[r] * D))[t];
        acc.x += v.x; acc.y += v.y; acc.z += v.z; acc.w += v.w;
    }
    ((float4*)(d_mus + (size_t)c * D))[t] = acc;

    // |mus|^2 block reduction
    red[t] = acc.x * acc.x + acc.y * acc.y + acc.z * acc.z + acc.w * acc.w;
    __syncthreads();
    for (int s = 128; s; s >>= 1) {
        if (t < s) red[t] += red[t + s];
        __syncthreads();
    }

    // S2c via warp 0 (fixed-tree, deterministic)
    if (t < 32) {
        float s = 0.f;
        for (int r = t; r < cnt; r += 32) s += d_s2[rows[r]];
        s = wsum(s);
        if (t == 0) {
            d_S2c[c] = s;
            d_cnt[c] = cnt;
            float m2 = red[0];
            d_mus2[c] = m2;
            float cc = fmaxf((float)cnt, 0.1f);
            d_invc[c] = 1.f / cc;
            d_pn2[c] = m2 / (cc * cc);
        }
    }
}

// ---------------- K3: dots = XQ @ MUS^T via tf32 mma.sync -----------------
// grid (NQ/128, KSP), block 256 (8 warps, 2Mx4N). Block tile 128x128.
// Warp tile 64x32 (4 mtiles x 4 ntiles of m16n8k8). Split-K over KPB=256.
__global__ __launch_bounds__(256) void k_dots(const float* __restrict__ xq) {
    __shared__ uint32_t As[128][36];   // padded stride 36: bank = 4r+c, conflict-free
    __shared__ uint32_t Bs[128][36];

    int qb = blockIdx.x * 128;
    int sp = blockIdx.y;
    int t = threadIdx.x;
    int lane = t & 31, wid = t >> 5;
    int wm = (wid >> 2) * 64;
    int wn = (wid & 3) * 32;
    int g = lane >> 2, ci = lane & 3;

    int lrow = t >> 1;
    int lcol0 = (t & 1) * 16;

    float acc[4][4][4];
#pragma unroll
    for (int a = 0; a < 4; a++)
#pragma unroll
        for (int b = 0; b < 4; b++)
#pragma unroll
            for (int r = 0; r < 4; r++) acc[a][b][r] = 0.f;

    const float* Aptr = xq + (size_t)(qb + lrow) * D + sp * KPB + lcol0;
    const float* Bptr = d_mus + (size_t)lrow * D + sp * KPB + lcol0;

    float4 aR[4], bR[4];
#pragma unroll
    for (int i = 0; i < 4; i++) {
        aR[i] = ((const float4*)Aptr)[i];
        bR[i] = ((const float4*)Bptr)[i];
    }

    for (int ch = 0; ch < KPB / CH; ch++) {
        __syncthreads();
#pragma unroll
        for (int i = 0; i < 4; i++) {
            uint4 ua, ub;
            ua.x = f2tf32(aR[i].x); ua.y = f2tf32(aR[i].y);
            ua.z = f2tf32(aR[i].z); ua.w = f2tf32(aR[i].w);
            ub.x = f2tf32(bR[i].x); ub.y = f2tf32(bR[i].y);
            ub.z = f2tf32(bR[i].z); ub.w = f2tf32(bR[i].w);
            *(uint4*)&As[lrow][lcol0 + 4 * i] = ua;
            *(uint4*)&Bs[lrow][lcol0 + 4 * i] = ub;
        }
        __syncthreads();
        if (ch + 1 < KPB / CH) {
            const float* An = Aptr + (ch + 1) * CH;
            const float* Bn = Bptr + (ch + 1) * CH;
#pragma unroll
            for (int i = 0; i < 4; i++) {
                aR[i] = ((const float4*)An)[i];
                bR[i] = ((const float4*)Bn)[i];
            }
        }
#pragma unroll
        for (int k0 = 0; k0 < CH; k0 += 8) {
            uint32_t af[4][4], bf[4][2];
#pragma unroll
            for (int mt = 0; mt < 4; mt++) {
                int r = wm + mt * 16 + g;
                af[mt][0] = As[r][k0 + ci];
                af[mt][1] = As[r + 8][k0 + ci];
                af[mt][2] = As[r][k0 + ci + 4];
                af[mt][3] = As[r + 8][k0 + ci + 4];
            }
#pragma unroll
            for (int nt = 0; nt < 4; nt++) {
                int r = wn + nt * 8 + g;
                bf[nt][0] = Bs[r][k0 + ci];
                bf[nt][1] = Bs[r][k0 + ci + 4];
            }
#pragma unroll
            for (int mt = 0; mt < 4; mt++)
#pragma unroll
                for (int nt = 0; nt < 4; nt++) {
                    asm volatile(
                        "mma.sync.aligned.m16n8k8.row.col.f32.tf32.tf32.f32 "
                        "{%0,%1,%2,%3}, {%4,%5,%6,%7}, {%8,%9}, {%0,%1,%2,%3};\n"
                        : "+f"(acc[mt][nt][0]), "+f"(acc[mt][nt][1]),
                          "+f"(acc[mt][nt][2]), "+f"(acc[mt][nt][3])
                        : "r"(af[mt][0]), "r"(af[mt][1]), "r"(af[mt][2]), "r"(af[mt][3]),
                          "r"(bf[nt][0]), "r"(bf[nt][1]));
                }
        }
    }

    // epilogue: write split partials
#pragma unroll
    for (int mt = 0; mt < 4; mt++)
#pragma unroll
        for (int nt = 0; nt < 4; nt++) {
            int row = qb + wm + mt * 16 + g;
            int col = wn + nt * 8 + 2 * ci;
            float* o = d_dotsp + ((size_t)sp * NQ + row) * KC + col;
            *(float2*)o = make_float2(acc[mt][nt][0], acc[mt][nt][1]);
            *(float2*)(o + 8 * KC) = make_float2(acc[mt][nt][2], acc[mt][nt][3]);
        }
}

// ---------------- K4: per-query logits + logsumexp + pos_logit ------------
// grid NQ, block KC(=128). Thread k owns class k. Split-K reduction inline.
__global__ void k_finalize(const int* __restrict__ yq, const int* __restrict__ ys,
                           const int* __restrict__ pos) {
    int i = blockIdx.x, k = threadIdx.x;
    float q2 = d_q2[i];
    int p = pos[i];
    int cnew = ys[p];

    float dot = 0.f;
#pragma unroll
    for (int s = 0; s < KSP; s++) dot += d_dotsp[((size_t)s * NQ + i) * KC + k];

    __shared__ float sdots[KC];
    sdots[k] = dot;

    float logit;
    if (k == cnew) {
        float Cc = fmaxf((float)d_cnt[cnew] - 1.f, 0.1f);
        float qp = (dot - q2) / Cc;
        float pp2 = (d_mus2[cnew] - 2.f * dot + q2) / (Cc * Cc);
        float dp2 = q2 - 2.f * qp + pp2;
        logit = -sqrtf(fmaxf(dp2, 0.f) + EPSF);
    } else {
        float d2 = fmaxf(q2 + d_pn2[k] - 2.f * dot * d_invc[k], 0.f);
        logit = -sqrtf(d2 + EPSF);
    }
    __shared__ float sh[4];
    int w = k >> 5, ln = k & 31;
    float m = wmax(logit);
    if (!ln) sh[w] = m;
    __syncthreads();
    float mall = fmaxf(fmaxf(sh[0], sh[1]), fmaxf(sh[2], sh[3]));
    float e = expf(logit - mall);
    float s = wsum(e);
    __syncthreads();
    if (!ln) sh[w] = s;
    __syncthreads();
    if (k == 0) {
        float tot = sh[0] + sh[1] + sh[2] + sh[3];
        float neg = mall + logf(tot);

        int cq = yq[i];
        float dotq = sdots[cq];
        int cntq = d_cnt[cq];
        float sumd2 = (float)cntq * q2 + d_S2c[cq] - 2.f * dotq;
        bool cmpos = (cq == cnew);
        bool idxf = cntq > 1;
        float numer = sumd2;
        float denom = (float)cntq;
        if (cmpos) {
            float d2self = fmaxf(q2 + d_s2[p] - 2.f * d_selfdot[i], 0.f);
            numer -= d2self;
            denom -= 1.f;
            if (!idxf) denom += 1.f;
        }
        float poslog = (denom > 0.f) ? (-0.5f * numer / denom) : 0.f;
        d_perq[i] = neg - poslog;
    }
}

// ---------------- K5: deterministic final mean ----------------------------
__global__ void k_loss(float* __restrict__ out) {
    int t = threadIdx.x;
    __shared__ float sh[1024];
    float v = d_perq[t] + d_perq[t + 1024] + d_perq[t + 2048] + d_perq[t + 3072];
    sh[t] = v;
    __syncthreads();
    for (int s = 512; s; s >>= 1) {
        if (t < s) sh[t] += sh[t + s];
        __syncthreads();
    }
    if (t == 0) out[0] = sh[0] * (1.f / (float)NQ);
}

// --------------------------------------------------------------------------
extern "C" void kernel_launch(void* const* d_in, const int* in_sizes, int n_in,
                              void* d_out, int out_size) {
    const float* xq  = (const float*)d_in[0];
    const int*   yq  = (const int*)d_in[1];
    const float* xs  = (const float*)d_in[2];
    const int*   ys  = (const int*)d_in[3];
    const int*   pos = (const int*)d_in[4];
    float* out = (float*)d_out;

    k_norms<<<NQ, 128>>>(xq, xs, pos);
    k_mus<<<KC, 256>>>(xs, ys);
    k_dots<<<dim3(NQ / 128, KSP), 256>>>(xq);
    k_finalize<<<NQ, KC>>>(yq, ys, pos);
    k_loss<<<1, 1024>>>(out);
}

// round 3
// speedup vs baseline: 2.6812x; 1.5290x over previous
#include <cuda_runtime.h>
#include <math.h>
#include <stdint.h>

#define NQ 4096
#define NS 4096
#define D  1024
#define KC 128
#define EPSF 1e-12f
#define KSP 4            // split-K for dots GEMM
#define KPB (D / KSP)    // 256 K per split
#define CH  32           // K chunk

// ---------------- device scratch ----------------
__device__ float d_s2[NS];
__device__ float d_q2[NQ];
__device__ float d_selfdot[NQ];
__device__ int   d_cnt[KC];
__device__ float d_S2c[KC];
__device__ float d_mus[KC * D];
__device__ float d_mus2[KC];
__device__ float d_pn2[KC];
__device__ float d_invc[KC];
__device__ float d_dotsp[KSP * NQ * KC];   // split-K partials
__device__ float d_perq[NQ];

// ---------------- helpers ----------------
__device__ __forceinline__ float wsum(float v) {
#pragma unroll
    for (int o = 16; o; o >>= 1) v += __shfl_xor_sync(0xffffffffu, v, o);
    return v;
}
__device__ __forceinline__ float wmax(float v) {
#pragma unroll
    for (int o = 16; o; o >>= 1) v = fmaxf(v, __shfl_xor_sync(0xffffffffu, v, o));
    return v;
}
__device__ __forceinline__ uint32_t f2tf32(float f) {
    uint32_t r;
    asm("cvt.rna.tf32.f32 %0, %1;" : "=r"(r) : "f"(f));
    return r;
}

// ---------------- K1: per-row norms + self dot (warp-per-row) -------------
// grid NQ/8, block 256. Warp w handles row i = blk*8 + w.
__global__ __launch_bounds__(256) void k_norms(const float* __restrict__ xq,
                                               const float* __restrict__ xs,
                                               const int* __restrict__ pos) {
    int i = blockIdx.x * 8 + (threadIdx.x >> 5);
    int ln = threadIdx.x & 31;
    int p = __ldg(pos + i);
    const float4* xr = (const float4*)(xs + (size_t)i * D);
    const float4* qr = (const float4*)(xq + (size_t)i * D);
    const float4* pr = (const float4*)(xs + (size_t)p * D);
    float s2 = 0.f, q2 = 0.f, sd = 0.f;
#pragma unroll
    for (int l = 0; l < 8; l++) {
        int idx = ln + 32 * l;
        float4 a = xr[idx];
        s2 += a.x * a.x + a.y * a.y + a.z * a.z + a.w * a.w;
        float4 q = qr[idx];
        q2 += q.x * q.x + q.y * q.y + q.z * q.z + q.w * q.w;
        float4 b = pr[idx];
        sd += q.x * b.x + q.y * b.y + q.z * b.z + q.w * b.w;
    }
    s2 = wsum(s2); q2 = wsum(q2); sd = wsum(sd);
    if (ln == 0) {
        d_s2[i] = s2;
        d_q2[i] = q2;
        d_selfdot[i] = sd;
    }
}

// ---------------- K2: fused per-class stats + feature sums ----------------
// grid KC, block 256. Ordered compaction of class rows, then direct
// accumulation of mus, cnt, S2c, |mus|^2, pn2, invc. Fully deterministic.
__global__ __launch_bounds__(256) void k_mus(const float* __restrict__ xs,
                                             const int* __restrict__ ys) {
    int c = blockIdx.x, t = threadIdx.x;
    __shared__ int rows[NS];
    __shared__ int sc[256];
    __shared__ float red[256];

    int myy[16];
    int j0 = t * 16;
#pragma unroll
    for (int j = 0; j < 16; j++) myy[j] = ys[j0 + j];
    int count = 0;
#pragma unroll
    for (int j = 0; j < 16; j++) count += (myy[j] == c);

    sc[t] = count;
    __syncthreads();
    for (int o = 1; o < 256; o <<= 1) {
        int v = (t >= o) ? sc[t - o] : 0;
        __syncthreads();
        sc[t] += v;
        __syncthreads();
    }
    int off = sc[t] - count;
    int cnt = sc[255];
#pragma unroll
    for (int j = 0; j < 16; j++) {
        if (myy[j] == c) rows[off++] = j0 + j;
    }
    __syncthreads();

    float4 acc = make_float4(0.f, 0.f, 0.f, 0.f);
    for (int r = 0; r < cnt; r++) {
        float4 v = ((const float4*)(xs + (size_t)rows[r] * D))[t];
        acc.x += v.x; acc.y += v.y; acc.z += v.z; acc.w += v.w;
    }
    ((float4*)(d_mus + (size_t)c * D))[t] = acc;

    red[t] = acc.x * acc.x + acc.y * acc.y + acc.z * acc.z + acc.w * acc.w;
    __syncthreads();
    for (int s = 128; s; s >>= 1) {
        if (t < s) red[t] += red[t + s];
        __syncthreads();
    }

    if (t < 32) {
        float s = 0.f;
        for (int r = t; r < cnt; r += 32) s += d_s2[rows[r]];
        s = wsum(s);
        if (t == 0) {
            d_S2c[c] = s;
            d_cnt[c] = cnt;
            float m2 = red[0];
            d_mus2[c] = m2;
            float cc = fmaxf((float)cnt, 0.1f);
            d_invc[c] = 1.f / cc;
            d_pn2[c] = m2 / (cc * cc);
        }
    }
}

// ---------------- K3: dots = XQ @ MUS^T via tf32 mma.sync -----------------
// grid (NQ/128, KSP), block 256 (8 warps, 2Mx4N). Block tile 128x128.
__global__ __launch_bounds__(256) void k_dots(const float* __restrict__ xq) {
    __shared__ uint32_t As[128][36];
    __shared__ uint32_t Bs[128][36];

    int qb = blockIdx.x * 128;
    int sp = blockIdx.y;
    int t = threadIdx.x;
    int lane = t & 31, wid = t >> 5;
    int wm = (wid >> 2) * 64;
    int wn = (wid & 3) * 32;
    int g = lane >> 2, ci = lane & 3;

    int lrow = t >> 1;
    int lcol0 = (t & 1) * 16;

    float acc[4][4][4];
#pragma unroll
    for (int a = 0; a < 4; a++)
#pragma unroll
        for (int b = 0; b < 4; b++)
#pragma unroll
            for (int r = 0; r < 4; r++) acc[a][b][r] = 0.f;

    const float* Aptr = xq + (size_t)(qb + lrow) * D + sp * KPB + lcol0;
    const float* Bptr = d_mus + (size_t)lrow * D + sp * KPB + lcol0;

    float4 aR[4], bR[4];
#pragma unroll
    for (int i = 0; i < 4; i++) {
        aR[i] = ((const float4*)Aptr)[i];
        bR[i] = ((const float4*)Bptr)[i];
    }

    for (int ch = 0; ch < KPB / CH; ch++) {
        __syncthreads();
#pragma unroll
        for (int i = 0; i < 4; i++) {
            uint4 ua, ub;
            ua.x = f2tf32(aR[i].x); ua.y = f2tf32(aR[i].y);
            ua.z = f2tf32(aR[i].z); ua.w = f2tf32(aR[i].w);
            ub.x = f2tf32(bR[i].x); ub.y = f2tf32(bR[i].y);
            ub.z = f2tf32(bR[i].z); ub.w = f2tf32(bR[i].w);
            *(uint4*)&As[lrow][lcol0 + 4 * i] = ua;
            *(uint4*)&Bs[lrow][lcol0 + 4 * i] = ub;
        }
        __syncthreads();
        if (ch + 1 < KPB / CH) {
            const float* An = Aptr + (ch + 1) * CH;
            const float* Bn = Bptr + (ch + 1) * CH;
#pragma unroll
            for (int i = 0; i < 4; i++) {
                aR[i] = ((const float4*)An)[i];
                bR[i] = ((const float4*)Bn)[i];
            }
        }
#pragma unroll
        for (int k0 = 0; k0 < CH; k0 += 8) {
            uint32_t af[4][4], bf[4][2];
#pragma unroll
            for (int mt = 0; mt < 4; mt++) {
                int r = wm + mt * 16 + g;
                af[mt][0] = As[r][k0 + ci];
                af[mt][1] = As[r + 8][k0 + ci];
                af[mt][2] = As[r][k0 + ci + 4];
                af[mt][3] = As[r + 8][k0 + ci + 4];
            }
#pragma unroll
            for (int nt = 0; nt < 4; nt++) {
                int r = wn + nt * 8 + g;
                bf[nt][0] = Bs[r][k0 + ci];
                bf[nt][1] = Bs[r][k0 + ci + 4];
            }
#pragma unroll
            for (int mt = 0; mt < 4; mt++)
#pragma unroll
                for (int nt = 0; nt < 4; nt++) {
                    asm volatile(
                        "mma.sync.aligned.m16n8k8.row.col.f32.tf32.tf32.f32 "
                        "{%0,%1,%2,%3}, {%4,%5,%6,%7}, {%8,%9}, {%0,%1,%2,%3};\n"
                        : "+f"(acc[mt][nt][0]), "+f"(acc[mt][nt][1]),
                          "+f"(acc[mt][nt][2]), "+f"(acc[mt][nt][3])
                        : "r"(af[mt][0]), "r"(af[mt][1]), "r"(af[mt][2]), "r"(af[mt][3]),
                          "r"(bf[nt][0]), "r"(bf[nt][1]));
                }
        }
    }

#pragma unroll
    for (int mt = 0; mt < 4; mt++)
#pragma unroll
        for (int nt = 0; nt < 4; nt++) {
            int row = qb + wm + mt * 16 + g;
            int col = wn + nt * 8 + 2 * ci;
            float* o = d_dotsp + ((size_t)sp * NQ + row) * KC + col;
            *(float2*)o = make_float2(acc[mt][nt][0], acc[mt][nt][1]);
            *(float2*)(o + 8 * KC) = make_float2(acc[mt][nt][2], acc[mt][nt][3]);
        }
}

// ---------------- K4: finalize, warp-per-query, shuffle-only --------------
// grid NQ/8, block 256. Warp handles query i; thread ln owns classes
// ln, ln+32, ln+64, ln+96. No shared memory, no __syncthreads.
__global__ __launch_bounds__(256) void k_finalize(const int* __restrict__ yq,
                                                  const int* __restrict__ ys,
                                                  const int* __restrict__ pos) {
    int i = blockIdx.x * 8 + (threadIdx.x >> 5);
    int ln = threadIdx.x & 31;
    float q2 = d_q2[i];
    int p = __ldg(pos + i);
    int cnew = __ldg(ys + p);
    int cq = __ldg(yq + i);

    float logit[4];
    float lmax = -1e30f;
    float dotq_c = 0.f;
#pragma unroll
    for (int kk = 0; kk < 4; kk++) {
        int k = ln + 32 * kk;
        float dot = 0.f;
#pragma unroll
        for (int s = 0; s < KSP; s++) dot += d_dotsp[((size_t)s * NQ + i) * KC + k];
        if (k == cq) dotq_c = dot;
        float lg;
        if (k == cnew) {
            float Cc = fmaxf((float)d_cnt[cnew] - 1.f, 0.1f);
            float qp = (dot - q2) / Cc;
            float pp2 = (d_mus2[cnew] - 2.f * dot + q2) / (Cc * Cc);
            float dp2 = q2 - 2.f * qp + pp2;
            lg = -sqrtf(fmaxf(dp2, 0.f) + EPSF);
        } else {
            float d2 = fmaxf(q2 + d_pn2[k] - 2.f * dot * d_invc[k], 0.f);
            lg = -sqrtf(d2 + EPSF);
        }
        logit[kk] = lg;
        lmax = fmaxf(lmax, lg);
    }
    float mall = wmax(lmax);
    float e = 0.f;
#pragma unroll
    for (int kk = 0; kk < 4; kk++) e += expf(logit[kk] - mall);
    float tot = wsum(e);
    float dotq = wsum(dotq_c);

    if (ln == 0) {
        float neg = mall + logf(tot);
        int cntq = d_cnt[cq];
        float sumd2 = (float)cntq * q2 + d_S2c[cq] - 2.f * dotq;
        bool cmpos = (cq == cnew);
        bool idxf = cntq > 1;
        float numer = sumd2;
        float denom = (float)cntq;
        if (cmpos) {
            float d2self = fmaxf(q2 + d_s2[p] - 2.f * d_selfdot[i], 0.f);
            numer -= d2self;
            denom -= 1.f;
            if (!idxf) denom += 1.f;
        }
        float poslog = (denom > 0.f) ? (-0.5f * numer / denom) : 0.f;
        d_perq[i] = neg - poslog;
    }
}

// ---------------- K5: deterministic final mean ----------------------------
__global__ void k_loss(float* __restrict__ out) {
    int t = threadIdx.x;
    __shared__ float sh[1024];
    float v = d_perq[t] + d_perq[t + 1024] + d_perq[t + 2048] + d_perq[t + 3072];
    sh[t] = v;
    __syncthreads();
    for (int s = 512; s; s >>= 1) {
        if (t < s) sh[t] += sh[t + s];
        __syncthreads();
    }
    if (t == 0) out[0] = sh[0] * (1.f / (float)NQ);
}

// --------------------------------------------------------------------------
extern "C" void kernel_launch(void* const* d_in, const int* in_sizes, int n_in,
                              void* d_out, int out_size) {
    const float* xq  = (const float*)d_in[0];
    const int*   yq  = (const int*)d_in[1];
    const float* xs  = (const float*)d_in[2];
    const int*   ys  = (const int*)d_in[3];
    const int*   pos = (const int*)d_in[4];
    float* out = (float*)d_out;

    k_norms<<<NQ / 8, 256>>>(xq, xs, pos);
    k_mus<<<KC, 256>>>(xs, ys);
    k_dots<<<dim3(NQ / 128, KSP), 256>>>(xq);
    k_finalize<<<NQ / 8, 256>>>(yq, ys, pos);
    k_loss<<<1, 1024>>>(out);
}